// round 1
// baseline (speedup 1.0000x reference)
#include <cuda_runtime.h>
#include <cuda_bf16.h>

#define BDIM 8192
#define IDIM 1024
#define HDIM 1024
#define KDIM 2048
#define NDIM 4096

#define BM 128
#define BN 128
#define BK 32
#define PAD 8

// Scratch for pre-activations [B, 4H] fp32 (128 MB). Static __device__ array:
// allocation-guard safe.
__device__ float g_pre[(size_t)BDIM * NDIM];

__device__ __forceinline__ void mma_bf16(float* d, const unsigned* a, const unsigned* b) {
    asm volatile(
        "mma.sync.aligned.m16n8k16.row.col.f32.bf16.bf16.f32 "
        "{%0,%1,%2,%3}, {%4,%5,%6,%7}, {%8,%9}, {%0,%1,%2,%3};\n"
        : "+f"(d[0]), "+f"(d[1]), "+f"(d[2]), "+f"(d[3])
        : "r"(a[0]), "r"(a[1]), "r"(a[2]), "r"(a[3]), "r"(b[0]), "r"(b[1]));
}

// pre = [inputs | h] @ W^T   via 3-term bf16-split MMA (fp32-grade accuracy)
__global__ __launch_bounds__(256) void gemm_kernel(
    const float* __restrict__ inp, const float* __restrict__ hmat,
    const float* __restrict__ W)
{
    __shared__ __align__(16) __nv_bfloat16 sAhi[BM][BK + PAD];
    __shared__ __align__(16) __nv_bfloat16 sAlo[BM][BK + PAD];
    __shared__ __align__(16) __nv_bfloat16 sBhi[BN][BK + PAD];
    __shared__ __align__(16) __nv_bfloat16 sBlo[BN][BK + PAD];

    const int tid  = threadIdx.x;
    const int lane = tid & 31;
    const int warp = tid >> 5;
    const int gid  = lane >> 2;   // 0..7
    const int tg   = lane & 3;    // 0..3
    const int warpM = warp >> 2;  // 0..1  -> 64-row slab
    const int warpN = warp & 3;   // 0..3  -> 32-col slab
    const int bM = blockIdx.y * BM;
    const int bN = blockIdx.x * BN;

    const int lr = tid >> 3;        // 0..31 (row base; +i*32)
    const int lc = (tid & 7) * 4;   // 0..28 (float4 col)

    float acc[4][4][4];
    #pragma unroll
    for (int i = 0; i < 4; i++)
        #pragma unroll
        for (int j = 0; j < 4; j++)
            #pragma unroll
            for (int k = 0; k < 4; k++) acc[i][j][k] = 0.f;

    float4 ra[4], rb[4];

    auto loadStage = [&](int k0) {
        const float* asrc;
        int ak;
        if (k0 < IDIM) { asrc = inp; ak = k0; } else { asrc = hmat; ak = k0 - IDIM; }
        #pragma unroll
        for (int i = 0; i < 4; i++) {
            int row = lr + i * 32;
            ra[i] = *(const float4*)(asrc + (size_t)(bM + row) * IDIM + ak + lc);
            rb[i] = *(const float4*)(W + (size_t)(bN + row) * KDIM + k0 + lc);
        }
    };

    auto storeStage = [&]() {
        #pragma unroll
        for (int i = 0; i < 4; i++) {
            int row = lr + i * 32;
            float av[4] = {ra[i].x, ra[i].y, ra[i].z, ra[i].w};
            float bv[4] = {rb[i].x, rb[i].y, rb[i].z, rb[i].w};
            #pragma unroll
            for (int j = 0; j < 4; j++) {
                __nv_bfloat16 h1 = __float2bfloat16(av[j]);
                sAhi[row][lc + j] = h1;
                sAlo[row][lc + j] = __float2bfloat16(av[j] - __bfloat162float(h1));
                __nv_bfloat16 h2 = __float2bfloat16(bv[j]);
                sBhi[row][lc + j] = h2;
                sBlo[row][lc + j] = __float2bfloat16(bv[j] - __bfloat162float(h2));
            }
        }
    };

    loadStage(0);
    storeStage();
    __syncthreads();

    const int NT = KDIM / BK;  // 64
    for (int t = 0; t < NT; ++t) {
        int k0 = (t + 1) * BK;
        if (k0 < KDIM) loadStage(k0);  // prefetch into regs, overlaps compute

        #pragma unroll
        for (int kk = 0; kk < BK; kk += 16) {
            unsigned ah[4][4], al[4][4], bh[4][2], bl[4][2];
            #pragma unroll
            for (int mf = 0; mf < 4; ++mf) {
                int r = warpM * 64 + mf * 16 + gid;
                int c = kk + tg * 2;
                ah[mf][0] = *(const unsigned*)&sAhi[r][c];
                ah[mf][1] = *(const unsigned*)&sAhi[r + 8][c];
                ah[mf][2] = *(const unsigned*)&sAhi[r][c + 8];
                ah[mf][3] = *(const unsigned*)&sAhi[r + 8][c + 8];
                al[mf][0] = *(const unsigned*)&sAlo[r][c];
                al[mf][1] = *(const unsigned*)&sAlo[r + 8][c];
                al[mf][2] = *(const unsigned*)&sAlo[r][c + 8];
                al[mf][3] = *(const unsigned*)&sAlo[r + 8][c + 8];
            }
            #pragma unroll
            for (int nf = 0; nf < 4; ++nf) {
                int n = warpN * 32 + nf * 8 + gid;
                int c = kk + tg * 2;
                bh[nf][0] = *(const unsigned*)&sBhi[n][c];
                bh[nf][1] = *(const unsigned*)&sBhi[n][c + 8];
                bl[nf][0] = *(const unsigned*)&sBlo[n][c];
                bl[nf][1] = *(const unsigned*)&sBlo[n][c + 8];
            }
            #pragma unroll
            for (int mf = 0; mf < 4; ++mf)
                #pragma unroll
                for (int nf = 0; nf < 4; ++nf) {
                    mma_bf16(acc[mf][nf], ah[mf], bh[nf]);  // hi*hi
                    mma_bf16(acc[mf][nf], ah[mf], bl[nf]);  // hi*lo
                    mma_bf16(acc[mf][nf], al[mf], bh[nf]);  // lo*hi
                }
        }
        __syncthreads();
        if (k0 < KDIM) {
            storeStage();
            __syncthreads();
        }
    }

    // write pre-activations
    #pragma unroll
    for (int mf = 0; mf < 4; ++mf) {
        int r = bM + warpM * 64 + mf * 16 + gid;
        #pragma unroll
        for (int nf = 0; nf < 4; ++nf) {
            int ccol = bN + warpN * 32 + nf * 8 + tg * 2;
            *(float2*)&g_pre[(size_t)r * NDIM + ccol] =
                make_float2(acc[mf][nf][0], acc[mf][nf][1]);
            *(float2*)&g_pre[(size_t)(r + 8) * NDIM + ccol] =
                make_float2(acc[mf][nf][2], acc[mf][nf][3]);
        }
    }
}

__device__ __forceinline__ void block_reduce2(float& s, float& ss,
                                              float* shs, float* shss, int tid) {
    #pragma unroll
    for (int o = 16; o > 0; o >>= 1) {
        s  += __shfl_xor_sync(0xffffffffu, s, o);
        ss += __shfl_xor_sync(0xffffffffu, ss, o);
    }
    __syncthreads();  // protect smem from previous use
    if ((tid & 31) == 0) { shs[tid >> 5] = s; shss[tid >> 5] = ss; }
    __syncthreads();
    s = 0.f; ss = 0.f;
    #pragma unroll
    for (int i = 0; i < 8; i++) { s += shs[i]; ss += shss[i]; }
}

// Fused 4-gate LN + activations + cell update + cell LN + outputs.
// One block per row (B=8192), 256 threads, thread owns 4 contiguous cols.
__global__ __launch_bounds__(256) void ln_kernel(
    const float* __restrict__ cin,
    const float* __restrict__ g4, const float* __restrict__ b4,
    const float* __restrict__ cg, const float* __restrict__ cb,
    float* __restrict__ outh, float* __restrict__ outc)
{
    __shared__ float shs[8], shss[8];
    const int b = blockIdx.x;
    const int tid = threadIdx.x;
    const int col = tid * 4;
    const float* rowp = g_pre + (size_t)b * NDIM;
    const float inv_h = 1.0f / (float)HDIM;

    float gate[4][4];
    #pragma unroll
    for (int g = 0; g < 4; ++g) {
        float4 x4 = *(const float4*)(rowp + g * HDIM + col);
        float x[4] = {x4.x, x4.y, x4.z, x4.w};
        float s  = x[0] + x[1] + x[2] + x[3];
        float ss = x[0]*x[0] + x[1]*x[1] + x[2]*x[2] + x[3]*x[3];
        block_reduce2(s, ss, shs, shss, tid);
        float mu   = s * inv_h;
        float var  = ss * inv_h - mu * mu;
        float rstd = rsqrtf(var + 1e-5f);
        float4 gm4 = *(const float4*)(g4 + g * HDIM + col);
        float4 bt4 = *(const float4*)(b4 + g * HDIM + col);
        float gm[4] = {gm4.x, gm4.y, gm4.z, gm4.w};
        float bt[4] = {bt4.x, bt4.y, bt4.z, bt4.w};
        #pragma unroll
        for (int j = 0; j < 4; j++) {
            float v = (x[j] - mu) * rstd * gm[j] + bt[j];
            gate[g][j] = (g == 1) ? tanhf(v) : 1.f / (1.f + __expf(-v));
        }
    }

    float4 c4 = *(const float4*)(cin + (size_t)b * HDIM + col);
    float cv[4] = {c4.x, c4.y, c4.z, c4.w};
    float cp[4];
    float s = 0.f, ss = 0.f;
    #pragma unroll
    for (int j = 0; j < 4; j++) {
        cp[j] = gate[0][j] * gate[1][j] + gate[2][j] * cv[j];
        s += cp[j];
        ss += cp[j] * cp[j];
    }
    block_reduce2(s, ss, shs, shss, tid);
    float mu   = s * inv_h;
    float var  = ss * inv_h - mu * mu;
    float rstd = rsqrtf(var + 1e-5f);

    float4 cg4 = *(const float4*)(cg + col);
    float4 cb4 = *(const float4*)(cb + col);
    float cgv[4] = {cg4.x, cg4.y, cg4.z, cg4.w};
    float cbv[4] = {cb4.x, cb4.y, cb4.z, cb4.w};

    float oh[4], oc[4];
    #pragma unroll
    for (int j = 0; j < 4; j++) {
        float nc = (cp[j] - mu) * rstd * cgv[j] + cbv[j];
        oc[j] = nc;
        oh[j] = gate[3][j] * tanhf(nc);
    }
    *(float4*)(outc + (size_t)b * HDIM + col) = make_float4(oc[0], oc[1], oc[2], oc[3]);
    *(float4*)(outh + (size_t)b * HDIM + col) = make_float4(oh[0], oh[1], oh[2], oh[3]);
}

extern "C" void kernel_launch(void* const* d_in, const int* in_sizes, int n_in,
                              void* d_out, int out_size) {
    const float* inp = (const float*)d_in[0];
    const float* h   = (const float*)d_in[1];
    const float* c   = (const float*)d_in[2];
    const float* W   = (const float*)d_in[3];
    const float* g4  = (const float*)d_in[4];
    const float* b4  = (const float*)d_in[5];
    const float* cg  = (const float*)d_in[6];
    const float* cb  = (const float*)d_in[7];
    float* out = (float*)d_out;

    dim3 grid(NDIM / BN, BDIM / BM);  // 32 x 64
    gemm_kernel<<<grid, 256>>>(inp, h, W);
    ln_kernel<<<BDIM, 256>>>(c, g4, b4, cg, cb,
                             out,                        // new_h
                             out + (size_t)BDIM * HDIM); // new_c
}

// round 6
// speedup vs baseline: 2.3316x; 2.3316x over previous
#include <cuda_runtime.h>
#include <cuda_bf16.h>
#include <cstdint>

#define BDIM 8192
#define IDIM 1024
#define HDIM 1024
#define KDIM 2048
#define NDIM 4096

#define TM 128
#define TN 128
#define BK 64
#define NT (KDIM / BK)   // 32 k-tiles

// Does THIS compilation pass support tcgen05 (arch-feature 'a' suffix)?
#if defined(__CUDA_ARCH__) && (defined(__CUDA_ARCH_FEAT_SM103_ALL) || defined(__CUDA_ARCH_FEAT_SM100_ALL) || defined(__CUDA_ARCH_FEAT_SM101_ALL))
#define USE_TCGEN05 1
#else
#define USE_TCGEN05 0
#endif

// ---------------- global scratch (static __device__: allocation-guard safe) ----
__device__ float g_pre[(size_t)BDIM * NDIM];                         // 128 MB
__device__ __align__(128) __nv_bfloat16 gAhi[(size_t)BDIM * KDIM];   // 32 MB
__device__ __align__(128) __nv_bfloat16 gAlo[(size_t)BDIM * KDIM];   // 32 MB
__device__ __align__(128) __nv_bfloat16 gWhi[(size_t)NDIM * KDIM];   // 16 MB
__device__ __align__(128) __nv_bfloat16 gWlo[(size_t)NDIM * KDIM];   // 16 MB

// ---------------- SMEM layout (shared by both paths) ---------------------------
// [0]      tmem base ptr (4B)        (tcgen05 path only)
// [16]     mbarrier (8B)             (tcgen05 path only)
// [1024..] 2 stages, each: Ahi 16K | Alo 16K | Bhi 16K | Blo 16K = 64K
#define SOFF_TILES   1024
#define REG_BYTES    (16 * 1024)
#define STAGE_BYTES  (4 * REG_BYTES)
#define OFF_AHI      0
#define OFF_ALO      (1 * REG_BYTES)
#define OFF_BHI      (2 * REG_BYTES)
#define OFF_BLO      (3 * REG_BYTES)
#define SMEM_TOTAL   (SOFF_TILES + 2 * STAGE_BYTES)   // 132 KB

// ---------------- common PTX helpers -------------------------------------------
__device__ __forceinline__ uint32_t smem_u32(const void* p) {
    uint32_t a;
    asm("{ .reg .u64 t; cvta.to.shared.u64 t, %1; cvt.u32.u64 %0, t; }" : "=r"(a) : "l"(p));
    return a;
}
__device__ __forceinline__ void cp16(uint32_t dst, const void* src) {
    asm volatile("cp.async.cg.shared.global [%0], [%1], 16;\n" :: "r"(dst), "l"(src));
}
__device__ __forceinline__ void cp_commit() {
    asm volatile("cp.async.commit_group;\n" ::: "memory");
}
__device__ __forceinline__ void cp_wait0() {
    asm volatile("cp.async.wait_group 0;\n" ::: "memory");
}
__device__ __forceinline__ void cp_wait1() {
    asm volatile("cp.async.wait_group 1;\n" ::: "memory");
}

// fill one SW128 K-major region: 128 rows x 128B (64 bf16)
__device__ __forceinline__ void fill_region(uint32_t sbase, const __nv_bfloat16* __restrict__ g,
                                            int grow0, int k0, int tid) {
    #pragma unroll
    for (int it = 0; it < 4; ++it) {
        int idx = tid + it * 256;
        int row = idx >> 3;
        int c = idx & 7;
        uint32_t off = (uint32_t)((row << 7) | (c << 4));
        uint32_t dst = sbase + (off ^ ((off >> 3) & 0x70));
        cp16(dst, g + (size_t)(grow0 + row) * KDIM + k0 + c * 8);
    }
}

#if USE_TCGEN05
// ---------------- tcgen05-only helpers -----------------------------------------
__device__ __forceinline__ uint32_t elect_one() {
    uint32_t p;
    asm volatile("{\n\t.reg .pred p;\n\telect.sync _|p, 0xFFFFFFFF;\n\tselp.b32 %0, 1, 0, p;\n\t}"
                 : "=r"(p));
    return p;
}
__device__ __forceinline__ uint64_t make_desc(uint32_t addr) {
    // SW128, Blackwell version=1, SBO=64 (1024B per 8-row block), LBO=1 (16B)
    return 0x4000404000010000ULL | (uint64_t)((addr >> 4) & 0x3FFF);
}
__device__ __forceinline__ void mma_f16_ss(uint32_t d_tmem, uint64_t da, uint64_t db,
                                           uint32_t idesc, uint32_t enable) {
    asm volatile(
        "{\n\t.reg .pred p;\n\t"
        "setp.ne.u32 p, %4, 0;\n\t"
        "tcgen05.mma.cta_group::1.kind::f16 [%0], %1, %2, %3, {%5, %5, %5, %5}, p;\n\t"
        "}\n"
        :: "r"(d_tmem), "l"(da), "l"(db), "r"(idesc), "r"(enable), "r"(0u)
        : "memory");
}
__device__ __forceinline__ void tc_commit(uint32_t mbar) {
    asm volatile(
        "tcgen05.commit.cta_group::1.mbarrier::arrive::one.shared::cluster.b64 [%0];"
        :: "r"(mbar) : "memory");
}
__device__ __forceinline__ void mbar_init(uint32_t mbar, uint32_t cnt) {
    asm volatile("mbarrier.init.shared.b64 [%0], %1;" :: "r"(mbar), "r"(cnt) : "memory");
}
__device__ __forceinline__ void mbar_wait(uint32_t mbar, uint32_t parity) {
    asm volatile(
        "{\n\t.reg .pred P1;\n\t"
        "WAIT_LOOP_%=:\n\t"
        "mbarrier.try_wait.parity.acquire.cta.shared::cta.b64 P1, [%0], %1, 0x989680;\n\t"
        "@P1 bra.uni WAIT_DONE_%=;\n\t"
        "bra.uni WAIT_LOOP_%=;\n\t"
        "WAIT_DONE_%=:\n\t}\n"
        :: "r"(mbar), "r"(parity) : "memory");
}
__device__ __forceinline__ void fence_async_smem() {
    asm volatile("fence.proxy.async.shared::cta;\n" ::: "memory");
}
#define TC_ALLOC(smem_addr, n) \
    asm volatile("tcgen05.alloc.cta_group::1.sync.aligned.shared::cta.b32 [%0], %1;" \
                 :: "r"(smem_addr), "r"((uint32_t)(n)) : "memory")
#define TC_DEALLOC(tmem, n) \
    asm volatile("tcgen05.dealloc.cta_group::1.sync.aligned.b32 %0, %1;" :: "r"(tmem), "r"((uint32_t)(n)))
#define TC_RELINQUISH() \
    asm volatile("tcgen05.relinquish_alloc_permit.cta_group::1.sync.aligned;")
#define TC_FENCE_AFTER()  asm volatile("tcgen05.fence::after_thread_sync;" ::: "memory")
#define TC_WAIT_LD()      asm volatile("tcgen05.wait::ld.sync.aligned;" ::: "memory")
#define TC_LD_X32(r, tmem_addr) \
    asm volatile( \
        "tcgen05.ld.sync.aligned.32x32b.x32.b32 " \
        "{%0, %1, %2, %3, %4, %5, %6, %7, " \
        " %8, %9, %10, %11, %12, %13, %14, %15, " \
        " %16, %17, %18, %19, %20, %21, %22, %23, " \
        " %24, %25, %26, %27, %28, %29, %30, %31}, [%32];" \
        : "=r"((r)[0]),  "=r"((r)[1]),  "=r"((r)[2]),  "=r"((r)[3]), \
          "=r"((r)[4]),  "=r"((r)[5]),  "=r"((r)[6]),  "=r"((r)[7]), \
          "=r"((r)[8]),  "=r"((r)[9]),  "=r"((r)[10]), "=r"((r)[11]), \
          "=r"((r)[12]), "=r"((r)[13]), "=r"((r)[14]), "=r"((r)[15]), \
          "=r"((r)[16]), "=r"((r)[17]), "=r"((r)[18]), "=r"((r)[19]), \
          "=r"((r)[20]), "=r"((r)[21]), "=r"((r)[22]), "=r"((r)[23]), \
          "=r"((r)[24]), "=r"((r)[25]), "=r"((r)[26]), "=r"((r)[27]), \
          "=r"((r)[28]), "=r"((r)[29]), "=r"((r)[30]), "=r"((r)[31]) \
        : "r"(tmem_addr))

// idesc kind::f16: dtype=F32(bit4), atype=BF16(bit7), btype=BF16(bit10), N/8<<17, M/16<<24
#define IDESC ((1u << 4) | (1u << 7) | (1u << 10) | ((TN / 8) << 17) | ((TM / 16) << 24))
#else
// ---------------- mma.sync-only helpers ----------------------------------------
__device__ __forceinline__ void mma_bf16(float* d, const unsigned* a, const unsigned* b) {
    asm volatile(
        "mma.sync.aligned.m16n8k16.row.col.f32.bf16.bf16.f32 "
        "{%0,%1,%2,%3}, {%4,%5,%6,%7}, {%8,%9}, {%0,%1,%2,%3};\n"
        : "+f"(d[0]), "+f"(d[1]), "+f"(d[2]), "+f"(d[3])
        : "r"(a[0]), "r"(a[1]), "r"(a[2]), "r"(a[3]), "r"(b[0]), "r"(b[1]));
}
__device__ __forceinline__ void ldsm_x4(uint32_t addr, uint32_t* r) {
    asm volatile("ldmatrix.sync.aligned.m8n8.x4.shared.b16 {%0,%1,%2,%3}, [%4];"
                 : "=r"(r[0]), "=r"(r[1]), "=r"(r[2]), "=r"(r[3]) : "r"(addr));
}
#endif

// ---------------- fp32 -> (hi,lo) bf16 split kernels ---------------------------
__device__ __forceinline__ void split4_store(__nv_bfloat16* __restrict__ hi,
                                             __nv_bfloat16* __restrict__ lo,
                                             size_t idx, float4 x) {
    float xs[4] = {x.x, x.y, x.z, x.w};
    uint32_t hp[2], lp[2];
    #pragma unroll
    for (int p = 0; p < 2; ++p) {
        __nv_bfloat16 h0 = __float2bfloat16(xs[2 * p]);
        __nv_bfloat16 h1 = __float2bfloat16(xs[2 * p + 1]);
        __nv_bfloat16 l0 = __float2bfloat16(xs[2 * p] - __bfloat162float(h0));
        __nv_bfloat16 l1 = __float2bfloat16(xs[2 * p + 1] - __bfloat162float(h1));
        hp[p] = (uint32_t)__bfloat16_as_ushort(h0) | ((uint32_t)__bfloat16_as_ushort(h1) << 16);
        lp[p] = (uint32_t)__bfloat16_as_ushort(l0) | ((uint32_t)__bfloat16_as_ushort(l1) << 16);
    }
    *(uint2*)(hi + idx) = make_uint2(hp[0], hp[1]);
    *(uint2*)(lo + idx) = make_uint2(lp[0], lp[1]);
}

__global__ __launch_bounds__(256) void conv_a_kernel(const float* __restrict__ inp,
                                                     const float* __restrict__ hmat) {
    size_t i = (size_t)blockIdx.x * blockDim.x + threadIdx.x;
    size_t idx = i * 4;
    if (idx >= (size_t)BDIM * KDIM) return;
    int r = (int)(idx >> 11);          // /KDIM
    int k = (int)(idx & (KDIM - 1));
    const float* src = (k < IDIM) ? (inp + (size_t)r * IDIM + k)
                                  : (hmat + (size_t)r * HDIM + (k - IDIM));
    split4_store(gAhi, gAlo, idx, *(const float4*)src);
}

__global__ __launch_bounds__(256) void conv_w_kernel(const float* __restrict__ W) {
    size_t i = (size_t)blockIdx.x * blockDim.x + threadIdx.x;
    size_t idx = i * 4;
    if (idx >= (size_t)NDIM * KDIM) return;
    split4_store(gWhi, gWlo, idx, *(const float4*)(W + idx));
}

// ---------------- GEMM: g_pre = [A] @ W^T  (3-pass bf16 split) -----------------
__global__ __launch_bounds__(256, 1) void gemm_kernel() {
    extern __shared__ __align__(1024) char smem[];
    uint32_t sb = smem_u32(smem);
    const int tid = threadIdx.x;
    const int warp = tid >> 5;
    const int lane = tid & 31;
    const int bM = blockIdx.y * TM;
    const int bN = blockIdx.x * TN;

#if USE_TCGEN05
    // ===================== tcgen05 path =====================
    if (warp == 0) TC_ALLOC(sb, 128);
    if (tid == 0) mbar_init(sb + 16, 1);
    __syncthreads();
    uint32_t tmem;
    asm volatile("ld.shared.b32 %0, [%1];" : "=r"(tmem) : "r"(sb));

    {   // prologue: fill tile 0 into stage 0
        uint32_t s0 = sb + SOFF_TILES;
        fill_region(s0 + OFF_AHI, gAhi, bM, 0, tid);
        fill_region(s0 + OFF_ALO, gAlo, bM, 0, tid);
        fill_region(s0 + OFF_BHI, gWhi, bN, 0, tid);
        fill_region(s0 + OFF_BLO, gWlo, bN, 0, tid);
        cp_commit();
    }

    for (int t = 0; t < NT; ++t) {
        const int s = t & 1;
        const uint32_t sbase = sb + SOFF_TILES + s * STAGE_BYTES;

        cp_wait0();           // tile t resident in stage s
        fence_async_smem();
        __syncthreads();

        if (warp == 0 && elect_one()) {
            uint64_t dAhi = make_desc(sbase + OFF_AHI);
            uint64_t dAlo = make_desc(sbase + OFF_ALO);
            uint64_t dBhi = make_desc(sbase + OFF_BHI);
            uint64_t dBlo = make_desc(sbase + OFF_BLO);
            #pragma unroll
            for (int k = 0; k < BK / 16; ++k)
                mma_f16_ss(tmem, dAhi + k * 2, dBhi + k * 2, IDESC, (t > 0) || (k > 0));
            #pragma unroll
            for (int k = 0; k < BK / 16; ++k)
                mma_f16_ss(tmem, dAhi + k * 2, dBlo + k * 2, IDESC, 1u);
            #pragma unroll
            for (int k = 0; k < BK / 16; ++k)
                mma_f16_ss(tmem, dAlo + k * 2, dBhi + k * 2, IDESC, 1u);
            tc_commit(sb + 16);
        }

        if (t > 0) mbar_wait(sb + 16, (uint32_t)((t - 1) & 1));  // MMA(t-1) done

        if (t + 1 < NT) {  // fill tile t+1 into stage s^1 (overlaps MMA(t))
            uint32_t sn = sb + SOFF_TILES + (s ^ 1) * STAGE_BYTES;
            int k0 = (t + 1) * BK;
            fill_region(sn + OFF_AHI, gAhi, bM, k0, tid);
            fill_region(sn + OFF_ALO, gAlo, bM, k0, tid);
            fill_region(sn + OFF_BHI, gWhi, bN, k0, tid);
            fill_region(sn + OFF_BLO, gWlo, bN, k0, tid);
            cp_commit();
        }
    }

    mbar_wait(sb + 16, (uint32_t)((NT - 1) & 1));
    TC_FENCE_AFTER();

    if (warp < 4) {  // 128 x 128 fp32 D -> g_pre
        float* dst_row = g_pre + (size_t)(bM + warp * 32 + lane) * NDIM + bN;
        #pragma unroll
        for (int ch = 0; ch < TN / 32; ++ch) {
            uint32_t r[32];
            TC_LD_X32(r, tmem + ch * 32);
            TC_WAIT_LD();
            #pragma unroll
            for (int j = 0; j < 8; ++j)
                *(float4*)(dst_row + ch * 32 + j * 4) =
                    make_float4(__uint_as_float(r[4 * j + 0]), __uint_as_float(r[4 * j + 1]),
                                __uint_as_float(r[4 * j + 2]), __uint_as_float(r[4 * j + 3]));
        }
    }
    __syncthreads();
    if (warp == 0) {
        TC_RELINQUISH();
        TC_DEALLOC(tmem, 128);
    }
#else
    // ===================== mma.sync fallback path =====================
    const int warpM = warp >> 2;   // 0..1 -> 64-row slab
    const int warpN = warp & 3;    // 0..3 -> 32-col slab

    float acc[4][4][4];
    #pragma unroll
    for (int i = 0; i < 4; i++)
        #pragma unroll
        for (int j = 0; j < 4; j++)
            #pragma unroll
            for (int k = 0; k < 4; k++) acc[i][j][k] = 0.f;

    // ldmatrix lane address components (SW128 layout: 128B rows, XOR swizzle)
    const uint32_t aRow = (uint32_t)(warpM * 64 + (lane & 15));        // + mf*16
    const uint32_t aSeg = (uint32_t)((lane >> 4) * 16);                // k-seg byte
    const uint32_t bRow = (uint32_t)(warpN * 32 + ((lane >> 1) & 8) + (lane & 7)); // + np*16
    const uint32_t bSeg = (uint32_t)(((lane >> 3) & 1) * 16);

    // prologue: fill tiles 0 and 1
    {
        uint32_t s0 = sb + SOFF_TILES;
        fill_region(s0 + OFF_AHI, gAhi, bM, 0, tid);
        fill_region(s0 + OFF_ALO, gAlo, bM, 0, tid);
        fill_region(s0 + OFF_BHI, gWhi, bN, 0, tid);
        fill_region(s0 + OFF_BLO, gWlo, bN, 0, tid);
        cp_commit();
        uint32_t s1 = sb + SOFF_TILES + STAGE_BYTES;
        fill_region(s1 + OFF_AHI, gAhi, bM, BK, tid);
        fill_region(s1 + OFF_ALO, gAlo, bM, BK, tid);
        fill_region(s1 + OFF_BHI, gWhi, bN, BK, tid);
        fill_region(s1 + OFF_BLO, gWlo, bN, BK, tid);
        cp_commit();
    }

    for (int t = 0; t < NT; ++t) {
        if (t == NT - 1) cp_wait0(); else cp_wait1();   // tile t resident
        __syncthreads();

        const uint32_t sbase = sb + SOFF_TILES + (t & 1) * STAGE_BYTES;

        #pragma unroll
        for (int kk = 0; kk < BK / 16; ++kk) {
            const uint32_t kByte = (uint32_t)(kk * 32);
            uint32_t ah[4][4], al[4][4], bh[2][4], bl[2][4];
            #pragma unroll
            for (int mf = 0; mf < 4; ++mf) {
                uint32_t row = aRow + mf * 16;
                uint32_t offR = row << 7;
                uint32_t adr = offR + ((kByte + aSeg) ^ ((row & 7) << 4));
                ldsm_x4(sbase + OFF_AHI + adr, ah[mf]);
                ldsm_x4(sbase + OFF_ALO + adr, al[mf]);
            }
            #pragma unroll
            for (int np = 0; np < 2; ++np) {
                uint32_t row = bRow + np * 16;
                uint32_t offR = row << 7;
                uint32_t adr = offR + ((kByte + bSeg) ^ ((row & 7) << 4));
                ldsm_x4(sbase + OFF_BHI + adr, bh[np]);
                ldsm_x4(sbase + OFF_BLO + adr, bl[np]);
            }
            #pragma unroll
            for (int mf = 0; mf < 4; ++mf)
                #pragma unroll
                for (int nf = 0; nf < 4; ++nf) {
                    const unsigned bhp[2] = {bh[nf >> 1][(nf & 1) * 2], bh[nf >> 1][(nf & 1) * 2 + 1]};
                    const unsigned blp[2] = {bl[nf >> 1][(nf & 1) * 2], bl[nf >> 1][(nf & 1) * 2 + 1]};
                    mma_bf16(acc[mf][nf], ah[mf], bhp);   // hi*hi
                    mma_bf16(acc[mf][nf], ah[mf], blp);   // hi*lo
                    mma_bf16(acc[mf][nf], al[mf], bhp);   // lo*hi
                }
        }
        __syncthreads();

        if (t + 2 < NT) {  // refill this stage with tile t+2
            int k0 = (t + 2) * BK;
            fill_region(sbase + OFF_AHI, gAhi, bM, k0, tid);
            fill_region(sbase + OFF_ALO, gAlo, bM, k0, tid);
            fill_region(sbase + OFF_BHI, gWhi, bN, k0, tid);
            fill_region(sbase + OFF_BLO, gWlo, bN, k0, tid);
            cp_commit();
        }
    }

    // write pre-activations
    const int gid = lane >> 2;
    const int tg  = lane & 3;
    #pragma unroll
    for (int mf = 0; mf < 4; ++mf) {
        int r = bM + warpM * 64 + mf * 16 + gid;
        #pragma unroll
        for (int nf = 0; nf < 4; ++nf) {
            int ccol = bN + warpN * 32 + nf * 8 + tg * 2;
            *(float2*)&g_pre[(size_t)r * NDIM + ccol] =
                make_float2(acc[mf][nf][0], acc[mf][nf][1]);
            *(float2*)&g_pre[(size_t)(r + 8) * NDIM + ccol] =
                make_float2(acc[mf][nf][2], acc[mf][nf][3]);
        }
    }
#endif
}

// ---------------- fused LN / gates / cell-update epilogue ----------------------
__device__ __forceinline__ float fsig(float v) {
    return __fdividef(1.f, 1.f + __expf(-v));
}
__device__ __forceinline__ float ftanh(float v) {
    return __fdividef(2.f, 1.f + __expf(-2.f * v)) - 1.f;
}

__device__ __forceinline__ void block_reduce2(float& s, float& ss,
                                              float* shs, float* shss, int tid) {
    #pragma unroll
    for (int o = 16; o > 0; o >>= 1) {
        s  += __shfl_xor_sync(0xffffffffu, s, o);
        ss += __shfl_xor_sync(0xffffffffu, ss, o);
    }
    __syncthreads();
    if ((tid & 31) == 0) { shs[tid >> 5] = s; shss[tid >> 5] = ss; }
    __syncthreads();
    s = 0.f; ss = 0.f;
    #pragma unroll
    for (int i = 0; i < 8; i++) { s += shs[i]; ss += shss[i]; }
}

__global__ __launch_bounds__(256) void ln_kernel(
    const float* __restrict__ cin,
    const float* __restrict__ g4, const float* __restrict__ b4,
    const float* __restrict__ cg, const float* __restrict__ cb,
    float* __restrict__ outh, float* __restrict__ outc)
{
    __shared__ float shs[8], shss[8];
    const int b = blockIdx.x;
    const int tid = threadIdx.x;
    const int col = tid * 4;
    const float* rowp = g_pre + (size_t)b * NDIM;
    const float inv_h = 1.0f / (float)HDIM;

    float gate[4][4];
    #pragma unroll
    for (int g = 0; g < 4; ++g) {
        float4 x4 = *(const float4*)(rowp + g * HDIM + col);
        float x[4] = {x4.x, x4.y, x4.z, x4.w};
        float s  = x[0] + x[1] + x[2] + x[3];
        float ss = x[0]*x[0] + x[1]*x[1] + x[2]*x[2] + x[3]*x[3];
        block_reduce2(s, ss, shs, shss, tid);
        float mu   = s * inv_h;
        float var  = ss * inv_h - mu * mu;
        float rstd = rsqrtf(var + 1e-5f);
        float4 gm4 = *(const float4*)(g4 + g * HDIM + col);
        float4 bt4 = *(const float4*)(b4 + g * HDIM + col);
        float gm[4] = {gm4.x, gm4.y, gm4.z, gm4.w};
        float bt[4] = {bt4.x, bt4.y, bt4.z, bt4.w};
        #pragma unroll
        for (int j = 0; j < 4; j++) {
            float v = (x[j] - mu) * rstd * gm[j] + bt[j];
            gate[g][j] = (g == 1) ? ftanh(v) : fsig(v);
        }
    }

    float4 c4 = *(const float4*)(cin + (size_t)b * HDIM + col);
    float cv[4] = {c4.x, c4.y, c4.z, c4.w};
    float cp[4];
    float s = 0.f, ss = 0.f;
    #pragma unroll
    for (int j = 0; j < 4; j++) {
        cp[j] = gate[0][j] * gate[1][j] + gate[2][j] * cv[j];
        s += cp[j];
        ss += cp[j] * cp[j];
    }
    block_reduce2(s, ss, shs, shss, tid);
    float mu   = s * inv_h;
    float var  = ss * inv_h - mu * mu;
    float rstd = rsqrtf(var + 1e-5f);

    float4 cg4 = *(const float4*)(cg + col);
    float4 cb4 = *(const float4*)(cb + col);
    float cgv[4] = {cg4.x, cg4.y, cg4.z, cg4.w};
    float cbv[4] = {cb4.x, cb4.y, cb4.z, cb4.w};

    float oh[4], oc[4];
    #pragma unroll
    for (int j = 0; j < 4; j++) {
        float nc = (cp[j] - mu) * rstd * cgv[j] + cbv[j];
        oc[j] = nc;
        oh[j] = gate[3][j] * ftanh(nc);
    }
    *(float4*)(outc + (size_t)b * HDIM + col) = make_float4(oc[0], oc[1], oc[2], oc[3]);
    *(float4*)(outh + (size_t)b * HDIM + col) = make_float4(oh[0], oh[1], oh[2], oh[3]);
}

// ---------------- launcher -----------------------------------------------------
extern "C" void kernel_launch(void* const* d_in, const int* in_sizes, int n_in,
                              void* d_out, int out_size) {
    const float* inp = (const float*)d_in[0];
    const float* h   = (const float*)d_in[1];
    const float* c   = (const float*)d_in[2];
    const float* W   = (const float*)d_in[3];
    const float* g4  = (const float*)d_in[4];
    const float* b4  = (const float*)d_in[5];
    const float* cg  = (const float*)d_in[6];
    const float* cb  = (const float*)d_in[7];
    float* out = (float*)d_out;

    cudaFuncSetAttribute(gemm_kernel,
                         cudaFuncAttributeMaxDynamicSharedMemorySize, SMEM_TOTAL);

    conv_a_kernel<<<(int)(((size_t)BDIM * KDIM / 4 + 255) / 256), 256>>>(inp, h);
    conv_w_kernel<<<(int)(((size_t)NDIM * KDIM / 4 + 255) / 256), 256>>>(W);

    dim3 grid(NDIM / TN, BDIM / TM);  // 32 x 64 = 2048 CTAs
    gemm_kernel<<<grid, 256, SMEM_TOTAL>>>();

    ln_kernel<<<BDIM, 256>>>(c, g4, b4, cg, cb,
                             out,                        // new_h
                             out + (size_t)BDIM * HDIM); // new_c
}

// round 16
// speedup vs baseline: 3.1854x; 1.3662x over previous
#include <cuda_runtime.h>
#include <cuda_bf16.h>
#include <cstdint>

#define BDIM 8192
#define IDIM 1024
#define HDIM 1024
#define KDIM 2048
#define NDIM 4096

#define TM 128
#define TN 256
#define BK 64
#define NT (KDIM / BK)   // 32 k-tiles

// Does THIS compilation pass support tcgen05 (arch-feature 'a' suffix)?
#if defined(__CUDA_ARCH__) && (defined(__CUDA_ARCH_FEAT_SM103_ALL) || defined(__CUDA_ARCH_FEAT_SM100_ALL) || defined(__CUDA_ARCH_FEAT_SM101_ALL))
#define USE_TCGEN05 1
#else
#define USE_TCGEN05 0
#endif

// ---------------- global scratch (static __device__: allocation-guard safe) ----
__device__ float g_pre[(size_t)BDIM * NDIM];                         // 128 MB
__device__ __align__(128) __nv_bfloat16 gAhi[(size_t)BDIM * KDIM];   // 32 MB
__device__ __align__(128) __nv_bfloat16 gAlo[(size_t)BDIM * KDIM];   // 32 MB
__device__ __align__(128) __nv_bfloat16 gWhi[(size_t)NDIM * KDIM];   // 16 MB
__device__ __align__(128) __nv_bfloat16 gWlo[(size_t)NDIM * KDIM];   // 16 MB

// ---------------- SMEM layout (shared by both paths) ---------------------------
// [0]      tmem base ptr (4B)        (tcgen05 path only)
// [16]     mbarrier (8B)             (tcgen05 path only)
// [1024..] 2 stages, each: Ahi 16K | Alo 16K | Bhi 32K | Blo 32K = 96K
#define SOFF_TILES   1024
#define OFF_AHI      0
#define OFF_ALO      (16 * 1024)
#define OFF_BHI      (32 * 1024)
#define OFF_BLO      (64 * 1024)
#define STAGE_BYTES  (96 * 1024)
#define SMEM_TOTAL   (SOFF_TILES + 2 * STAGE_BYTES)   // ~193 KB

// ---------------- common PTX helpers -------------------------------------------
__device__ __forceinline__ uint32_t smem_u32(const void* p) {
    uint32_t a;
    asm("{ .reg .u64 t; cvta.to.shared.u64 t, %1; cvt.u32.u64 %0, t; }" : "=r"(a) : "l"(p));
    return a;
}
__device__ __forceinline__ void cp16(uint32_t dst, const void* src) {
    asm volatile("cp.async.cg.shared.global [%0], [%1], 16;\n" :: "r"(dst), "l"(src));
}
__device__ __forceinline__ void cp_commit() {
    asm volatile("cp.async.commit_group;\n" ::: "memory");
}
__device__ __forceinline__ void cp_wait0() {
    asm volatile("cp.async.wait_group 0;\n" ::: "memory");
}
__device__ __forceinline__ void cp_wait1() {
    asm volatile("cp.async.wait_group 1;\n" ::: "memory");
}

// fill one SW128 K-major region: R rows x 128B (64 bf16)
template <int R>
__device__ __forceinline__ void fill_region(uint32_t sbase, const __nv_bfloat16* __restrict__ g,
                                            int grow0, int k0, int tid) {
    #pragma unroll
    for (int it = 0; it < (R * 8) / 256; ++it) {
        int idx = tid + it * 256;
        int row = idx >> 3;
        int c = idx & 7;
        uint32_t off = (uint32_t)((row << 7) | (c << 4));
        uint32_t dst = sbase + (off ^ ((off >> 3) & 0x70));
        cp16(dst, g + (size_t)(grow0 + row) * KDIM + k0 + c * 8);
    }
}

#if USE_TCGEN05
// ---------------- tcgen05-only helpers -----------------------------------------
__device__ __forceinline__ uint32_t elect_one() {
    uint32_t p;
    asm volatile("{\n\t.reg .pred p;\n\telect.sync _|p, 0xFFFFFFFF;\n\tselp.b32 %0, 1, 0, p;\n\t}"
                 : "=r"(p));
    return p;
}
__device__ __forceinline__ uint64_t make_desc(uint32_t addr) {
    // SW128, Blackwell version=1, SBO=64 (1024B per 8-row block), LBO=1 (16B)
    return 0x4000404000010000ULL | (uint64_t)((addr >> 4) & 0x3FFF);
}
__device__ __forceinline__ void mma_f16_ss(uint32_t d_tmem, uint64_t da, uint64_t db,
                                           uint32_t idesc, uint32_t enable) {
    asm volatile(
        "{\n\t.reg .pred p;\n\t"
        "setp.ne.u32 p, %4, 0;\n\t"
        "tcgen05.mma.cta_group::1.kind::f16 [%0], %1, %2, %3, {%5, %5, %5, %5}, p;\n\t"
        "}\n"
        :: "r"(d_tmem), "l"(da), "l"(db), "r"(idesc), "r"(enable), "r"(0u)
        : "memory");
}
__device__ __forceinline__ void tc_commit(uint32_t mbar) {
    asm volatile(
        "tcgen05.commit.cta_group::1.mbarrier::arrive::one.shared::cluster.b64 [%0];"
        :: "r"(mbar) : "memory");
}
__device__ __forceinline__ void mbar_init(uint32_t mbar, uint32_t cnt) {
    asm volatile("mbarrier.init.shared.b64 [%0], %1;" :: "r"(mbar), "r"(cnt) : "memory");
}
__device__ __forceinline__ void mbar_wait(uint32_t mbar, uint32_t parity) {
    asm volatile(
        "{\n\t.reg .pred P1;\n\t"
        "WAIT_LOOP_%=:\n\t"
        "mbarrier.try_wait.parity.acquire.cta.shared::cta.b64 P1, [%0], %1, 0x989680;\n\t"
        "@P1 bra.uni WAIT_DONE_%=;\n\t"
        "bra.uni WAIT_LOOP_%=;\n\t"
        "WAIT_DONE_%=:\n\t}\n"
        :: "r"(mbar), "r"(parity) : "memory");
}
__device__ __forceinline__ void fence_async_smem() {
    asm volatile("fence.proxy.async.shared::cta;\n" ::: "memory");
}
#define TC_ALLOC(smem_addr, n) \
    asm volatile("tcgen05.alloc.cta_group::1.sync.aligned.shared::cta.b32 [%0], %1;" \
                 :: "r"(smem_addr), "r"((uint32_t)(n)) : "memory")
#define TC_DEALLOC(tmem, n) \
    asm volatile("tcgen05.dealloc.cta_group::1.sync.aligned.b32 %0, %1;" :: "r"(tmem), "r"((uint32_t)(n)))
#define TC_RELINQUISH() \
    asm volatile("tcgen05.relinquish_alloc_permit.cta_group::1.sync.aligned;")
#define TC_FENCE_AFTER()  asm volatile("tcgen05.fence::after_thread_sync;" ::: "memory")
#define TC_WAIT_LD()      asm volatile("tcgen05.wait::ld.sync.aligned;" ::: "memory")
#define TC_LD_X32(r, tmem_addr) \
    asm volatile( \
        "tcgen05.ld.sync.aligned.32x32b.x32.b32 " \
        "{%0, %1, %2, %3, %4, %5, %6, %7, " \
        " %8, %9, %10, %11, %12, %13, %14, %15, " \
        " %16, %17, %18, %19, %20, %21, %22, %23, " \
        " %24, %25, %26, %27, %28, %29, %30, %31}, [%32];" \
        : "=r"((r)[0]),  "=r"((r)[1]),  "=r"((r)[2]),  "=r"((r)[3]), \
          "=r"((r)[4]),  "=r"((r)[5]),  "=r"((r)[6]),  "=r"((r)[7]), \
          "=r"((r)[8]),  "=r"((r)[9]),  "=r"((r)[10]), "=r"((r)[11]), \
          "=r"((r)[12]), "=r"((r)[13]), "=r"((r)[14]), "=r"((r)[15]), \
          "=r"((r)[16]), "=r"((r)[17]), "=r"((r)[18]), "=r"((r)[19]), \
          "=r"((r)[20]), "=r"((r)[21]), "=r"((r)[22]), "=r"((r)[23]), \
          "=r"((r)[24]), "=r"((r)[25]), "=r"((r)[26]), "=r"((r)[27]), \
          "=r"((r)[28]), "=r"((r)[29]), "=r"((r)[30]), "=r"((r)[31]) \
        : "r"(tmem_addr))

// idesc kind::f16: dtype=F32(bit4), atype=BF16(bit7), btype=BF16(bit10), N/8<<17, M/16<<24
#define IDESC ((1u << 4) | (1u << 7) | (1u << 10) | ((TN / 8) << 17) | ((TM / 16) << 24))
#else
// ---------------- mma.sync-only helpers ----------------------------------------
__device__ __forceinline__ void mma_bf16(float* d, const unsigned* a, const unsigned* b) {
    asm volatile(
        "mma.sync.aligned.m16n8k16.row.col.f32.bf16.bf16.f32 "
        "{%0,%1,%2,%3}, {%4,%5,%6,%7}, {%8,%9}, {%0,%1,%2,%3};\n"
        : "+f"(d[0]), "+f"(d[1]), "+f"(d[2]), "+f"(d[3])
        : "r"(a[0]), "r"(a[1]), "r"(a[2]), "r"(a[3]), "r"(b[0]), "r"(b[1]));
}
__device__ __forceinline__ void ldsm_x4(uint32_t addr, uint32_t* r) {
    asm volatile("ldmatrix.sync.aligned.m8n8.x4.shared.b16 {%0,%1,%2,%3}, [%4];"
                 : "=r"(r[0]), "=r"(r[1]), "=r"(r[2]), "=r"(r[3]) : "r"(addr));
}
#endif

// ---------------- fp32 -> (hi,lo) bf16 split kernels ---------------------------
__device__ __forceinline__ void split4_store(__nv_bfloat16* __restrict__ hi,
                                             __nv_bfloat16* __restrict__ lo,
                                             size_t idx, float4 x) {
    float xs[4] = {x.x, x.y, x.z, x.w};
    uint32_t hp[2], lp[2];
    #pragma unroll
    for (int p = 0; p < 2; ++p) {
        __nv_bfloat16 h0 = __float2bfloat16(xs[2 * p]);
        __nv_bfloat16 h1 = __float2bfloat16(xs[2 * p + 1]);
        __nv_bfloat16 l0 = __float2bfloat16(xs[2 * p] - __bfloat162float(h0));
        __nv_bfloat16 l1 = __float2bfloat16(xs[2 * p + 1] - __bfloat162float(h1));
        hp[p] = (uint32_t)__bfloat16_as_ushort(h0) | ((uint32_t)__bfloat16_as_ushort(h1) << 16);
        lp[p] = (uint32_t)__bfloat16_as_ushort(l0) | ((uint32_t)__bfloat16_as_ushort(l1) << 16);
    }
    *(uint2*)(hi + idx) = make_uint2(hp[0], hp[1]);
    *(uint2*)(lo + idx) = make_uint2(lp[0], lp[1]);
}

__global__ __launch_bounds__(256) void conv_a_kernel(const float* __restrict__ inp,
                                                     const float* __restrict__ hmat) {
    size_t i = (size_t)blockIdx.x * blockDim.x + threadIdx.x;
    size_t idx = i * 4;
    if (idx >= (size_t)BDIM * KDIM) return;
    int r = (int)(idx >> 11);          // /KDIM
    int k = (int)(idx & (KDIM - 1));
    const float* src = (k < IDIM) ? (inp + (size_t)r * IDIM + k)
                                  : (hmat + (size_t)r * HDIM + (k - IDIM));
    split4_store(gAhi, gAlo, idx, *(const float4*)src);
}

__global__ __launch_bounds__(256) void conv_w_kernel(const float* __restrict__ W) {
    size_t i = (size_t)blockIdx.x * blockDim.x + threadIdx.x;
    size_t idx = i * 4;
    if (idx >= (size_t)NDIM * KDIM) return;
    split4_store(gWhi, gWlo, idx, *(const float4*)(W + idx));
}

// ---------------- GEMM: g_pre = [A] @ W^T  (3-pass bf16 split) -----------------
__global__ __launch_bounds__(256, 1) void gemm_kernel() {
    extern __shared__ __align__(1024) char smem[];
    uint32_t sb = smem_u32(smem);
    const int tid = threadIdx.x;
    const int warp = tid >> 5;
    const int lane = tid & 31;
    const int bM = blockIdx.y * TM;
    const int bN = blockIdx.x * TN;

#if USE_TCGEN05
    // ===================== tcgen05 path =====================
    if (warp == 0) TC_ALLOC(sb, 256);
    if (tid == 0) mbar_init(sb + 16, 1);
    __syncthreads();
    uint32_t tmem;
    asm volatile("ld.shared.b32 %0, [%1];" : "=r"(tmem) : "r"(sb));

    {   // prologue: fill tile 0 into stage 0
        uint32_t s0 = sb + SOFF_TILES;
        fill_region<TM>(s0 + OFF_AHI, gAhi, bM, 0, tid);
        fill_region<TM>(s0 + OFF_ALO, gAlo, bM, 0, tid);
        fill_region<TN>(s0 + OFF_BHI, gWhi, bN, 0, tid);
        fill_region<TN>(s0 + OFF_BLO, gWlo, bN, 0, tid);
        cp_commit();
    }

    for (int t = 0; t < NT; ++t) {
        const int s = t & 1;
        const uint32_t sbase = sb + SOFF_TILES + s * STAGE_BYTES;

        cp_wait0();           // tile t resident in stage s
        fence_async_smem();
        __syncthreads();

        if (warp == 0 && elect_one()) {
            uint64_t dAhi = make_desc(sbase + OFF_AHI);
            uint64_t dAlo = make_desc(sbase + OFF_ALO);
            uint64_t dBhi = make_desc(sbase + OFF_BHI);
            uint64_t dBlo = make_desc(sbase + OFF_BLO);
            #pragma unroll
            for (int k = 0; k < BK / 16; ++k)
                mma_f16_ss(tmem, dAhi + k * 2, dBhi + k * 2, IDESC, (t > 0) || (k > 0));
            #pragma unroll
            for (int k = 0; k < BK / 16; ++k)
                mma_f16_ss(tmem, dAhi + k * 2, dBlo + k * 2, IDESC, 1u);
            #pragma unroll
            for (int k = 0; k < BK / 16; ++k)
                mma_f16_ss(tmem, dAlo + k * 2, dBhi + k * 2, IDESC, 1u);
            tc_commit(sb + 16);
        }

        if (t > 0) mbar_wait(sb + 16, (uint32_t)((t - 1) & 1));  // MMA(t-1) done

        if (t + 1 < NT) {  // fill tile t+1 into stage s^1 (overlaps MMA(t))
            uint32_t sn = sb + SOFF_TILES + (s ^ 1) * STAGE_BYTES;
            int k0 = (t + 1) * BK;
            fill_region<TM>(sn + OFF_AHI, gAhi, bM, k0, tid);
            fill_region<TM>(sn + OFF_ALO, gAlo, bM, k0, tid);
            fill_region<TN>(sn + OFF_BHI, gWhi, bN, k0, tid);
            fill_region<TN>(sn + OFF_BLO, gWlo, bN, k0, tid);
            cp_commit();
        }
    }

    mbar_wait(sb + 16, (uint32_t)((NT - 1) & 1));
    TC_FENCE_AFTER();

    if (warp < 4) {  // 128 x 256 fp32 D -> g_pre
        float* dst_row = g_pre + (size_t)(bM + warp * 32 + lane) * NDIM + bN;
        #pragma unroll
        for (int ch = 0; ch < TN / 32; ++ch) {
            uint32_t r[32];
            TC_LD_X32(r, tmem + ch * 32);
            TC_WAIT_LD();
            #pragma unroll
            for (int j = 0; j < 8; ++j)
                *(float4*)(dst_row + ch * 32 + j * 4) =
                    make_float4(__uint_as_float(r[4 * j + 0]), __uint_as_float(r[4 * j + 1]),
                                __uint_as_float(r[4 * j + 2]), __uint_as_float(r[4 * j + 3]));
        }
    }
    __syncthreads();
    if (warp == 0) {
        TC_RELINQUISH();
        TC_DEALLOC(tmem, 256);
    }
#else
    // ===================== mma.sync fallback path =====================
    const int warpM = warp >> 2;   // 0..1 -> 64-row slab
    const int warpN = warp & 3;    // 0..3 -> 64-col slab

    float acc[4][8][4];
    #pragma unroll
    for (int i = 0; i < 4; i++)
        #pragma unroll
        for (int j = 0; j < 8; j++)
            #pragma unroll
            for (int k = 0; k < 4; k++) acc[i][j][k] = 0.f;

    // ldmatrix lane address components (SW128 layout: 128B rows, XOR swizzle)
    const uint32_t aRow = (uint32_t)(warpM * 64 + (lane & 15));        // + mf*16
    const uint32_t aSeg = (uint32_t)((lane >> 4) * 16);                // k-seg byte
    const uint32_t bRow = (uint32_t)(warpN * 64 + ((lane >> 1) & 8) + (lane & 7)); // + half*32 + np*16
    const uint32_t bSeg = (uint32_t)(((lane >> 3) & 1) * 16);

    // prologue: fill tiles 0 and 1
    {
        uint32_t s0 = sb + SOFF_TILES;
        fill_region<TM>(s0 + OFF_AHI, gAhi, bM, 0, tid);
        fill_region<TM>(s0 + OFF_ALO, gAlo, bM, 0, tid);
        fill_region<TN>(s0 + OFF_BHI, gWhi, bN, 0, tid);
        fill_region<TN>(s0 + OFF_BLO, gWlo, bN, 0, tid);
        cp_commit();
        uint32_t s1 = sb + SOFF_TILES + STAGE_BYTES;
        fill_region<TM>(s1 + OFF_AHI, gAhi, bM, BK, tid);
        fill_region<TM>(s1 + OFF_ALO, gAlo, bM, BK, tid);
        fill_region<TN>(s1 + OFF_BHI, gWhi, bN, BK, tid);
        fill_region<TN>(s1 + OFF_BLO, gWlo, bN, BK, tid);
        cp_commit();
    }

    for (int t = 0; t < NT; ++t) {
        if (t == NT - 1) cp_wait0(); else cp_wait1();   // tile t resident
        __syncthreads();

        const uint32_t sbase = sb + SOFF_TILES + (t & 1) * STAGE_BYTES;

        #pragma unroll
        for (int kk = 0; kk < BK / 16; ++kk) {
            const uint32_t kByte = (uint32_t)(kk * 32);
            uint32_t ah[4][4], al[4][4];
            #pragma unroll
            for (int mf = 0; mf < 4; ++mf) {
                uint32_t row = aRow + mf * 16;
                uint32_t offR = row << 7;
                uint32_t adr = offR + ((kByte + aSeg) ^ ((row & 7) << 4));
                ldsm_x4(sbase + OFF_AHI + adr, ah[mf]);
                ldsm_x4(sbase + OFF_ALO + adr, al[mf]);
            }
            #pragma unroll
            for (int half = 0; half < 2; ++half) {   // 32 cols per half
                uint32_t bh[2][4], bl[2][4];
                #pragma unroll
                for (int np = 0; np < 2; ++np) {
                    uint32_t row = bRow + half * 32 + np * 16;
                    uint32_t offR = row << 7;
                    uint32_t adr = offR + ((kByte + bSeg) ^ ((row & 7) << 4));
                    ldsm_x4(sbase + OFF_BHI + adr, bh[np]);
                    ldsm_x4(sbase + OFF_BLO + adr, bl[np]);
                }
                #pragma unroll
                for (int mf = 0; mf < 4; ++mf)
                    #pragma unroll
                    for (int nfl = 0; nfl < 4; ++nfl) {
                        const int nf = half * 4 + nfl;
                        const unsigned bhp[2] = {bh[nfl >> 1][(nfl & 1) * 2], bh[nfl >> 1][(nfl & 1) * 2 + 1]};
                        const unsigned blp[2] = {bl[nfl >> 1][(nfl & 1) * 2], bl[nfl >> 1][(nfl & 1) * 2 + 1]};
                        mma_bf16(acc[mf][nf], ah[mf], bhp);   // hi*hi
                        mma_bf16(acc[mf][nf], ah[mf], blp);   // hi*lo
                        mma_bf16(acc[mf][nf], al[mf], bhp);   // lo*hi
                    }
            }
        }
        __syncthreads();

        if (t + 2 < NT) {  // refill this stage with tile t+2
            int k0 = (t + 2) * BK;
            fill_region<TM>(sbase + OFF_AHI, gAhi, bM, k0, tid);
            fill_region<TM>(sbase + OFF_ALO, gAlo, bM, k0, tid);
            fill_region<TN>(sbase + OFF_BHI, gWhi, bN, k0, tid);
            fill_region<TN>(sbase + OFF_BLO, gWlo, bN, k0, tid);
            cp_commit();
        }
    }

    // write pre-activations
    const int gid = lane >> 2;
    const int tg  = lane & 3;
    #pragma unroll
    for (int mf = 0; mf < 4; ++mf) {
        int r = bM + warpM * 64 + mf * 16 + gid;
        #pragma unroll
        for (int nf = 0; nf < 8; ++nf) {
            int ccol = bN + warpN * 64 + nf * 8 + tg * 2;
            *(float2*)&g_pre[(size_t)r * NDIM + ccol] =
                make_float2(acc[mf][nf][0], acc[mf][nf][1]);
            *(float2*)&g_pre[(size_t)(r + 8) * NDIM + ccol] =
                make_float2(acc[mf][nf][2], acc[mf][nf][3]);
        }
    }
#endif
}

// ---------------- fused LN / gates / cell-update epilogue ----------------------
__device__ __forceinline__ float fsig(float v) {
    return __fdividef(1.f, 1.f + __expf(-v));
}
__device__ __forceinline__ float ftanh(float v) {
    return __fdividef(2.f, 1.f + __expf(-2.f * v)) - 1.f;
}

// One block per row (B=8192), 256 threads, thread owns 4 contiguous cols/gate.
// All 4 gate (sum, sumsq) pairs reduced in a single block-reduction round.
__global__ __launch_bounds__(256) void ln_kernel(
    const float* __restrict__ cin,
    const float* __restrict__ g4, const float* __restrict__ b4,
    const float* __restrict__ cg, const float* __restrict__ cb,
    float* __restrict__ outh, float* __restrict__ outc)
{
    __shared__ float sh[10][8];   // [4 gates x (s,ss) + cell (s,ss)][8 warps]
    const int b = blockIdx.x;
    const int tid = threadIdx.x;
    const int wid = tid >> 5;
    const int col = tid * 4;
    const float* rowp = g_pre + (size_t)b * NDIM;
    const float inv_h = 1.0f / (float)HDIM;

    // 1) load all 4 gates, accumulate per-thread partial sums
    float x[4][4];
    float s4[4], ss4[4];
    #pragma unroll
    for (int g = 0; g < 4; ++g) {
        float4 x4 = *(const float4*)(rowp + g * HDIM + col);
        x[g][0] = x4.x; x[g][1] = x4.y; x[g][2] = x4.z; x[g][3] = x4.w;
        s4[g]  = x4.x + x4.y + x4.z + x4.w;
        ss4[g] = x4.x*x4.x + x4.y*x4.y + x4.z*x4.z + x4.w*x4.w;
    }

    // single warp-reduce round over 8 values
    #pragma unroll
    for (int o = 16; o > 0; o >>= 1) {
        #pragma unroll
        for (int g = 0; g < 4; ++g) {
            s4[g]  += __shfl_xor_sync(0xffffffffu, s4[g], o);
            ss4[g] += __shfl_xor_sync(0xffffffffu, ss4[g], o);
        }
    }
    if ((tid & 31) == 0) {
        #pragma unroll
        for (int g = 0; g < 4; ++g) { sh[2*g][wid] = s4[g]; sh[2*g+1][wid] = ss4[g]; }
    }
    __syncthreads();

    float mu[4], rstd[4];
    #pragma unroll
    for (int g = 0; g < 4; ++g) {
        float s = 0.f, ss = 0.f;
        #pragma unroll
        for (int i = 0; i < 8; i++) { s += sh[2*g][i]; ss += sh[2*g+1][i]; }
        mu[g] = s * inv_h;
        float var = ss * inv_h - mu[g] * mu[g];
        rstd[g] = rsqrtf(var + 1e-5f);
    }

    // 2) gates
    float gate[4][4];
    #pragma unroll
    for (int g = 0; g < 4; ++g) {
        float4 gm4 = *(const float4*)(g4 + g * HDIM + col);
        float4 bt4 = *(const float4*)(b4 + g * HDIM + col);
        float gm[4] = {gm4.x, gm4.y, gm4.z, gm4.w};
        float bt[4] = {bt4.x, bt4.y, bt4.z, bt4.w};
        #pragma unroll
        for (int j = 0; j < 4; j++) {
            float v = (x[g][j] - mu[g]) * rstd[g] * gm[j] + bt[j];
            gate[g][j] = (g == 1) ? ftanh(v) : fsig(v);
        }
    }

    // 3) cell update + its LN
    float4 c4 = *(const float4*)(cin + (size_t)b * HDIM + col);
    float cv[4] = {c4.x, c4.y, c4.z, c4.w};
    float cp[4];
    float s = 0.f, ss = 0.f;
    #pragma unroll
    for (int j = 0; j < 4; j++) {
        cp[j] = gate[0][j] * gate[1][j] + gate[2][j] * cv[j];
        s += cp[j];
        ss += cp[j] * cp[j];
    }
    #pragma unroll
    for (int o = 16; o > 0; o >>= 1) {
        s  += __shfl_xor_sync(0xffffffffu, s, o);
        ss += __shfl_xor_sync(0xffffffffu, ss, o);
    }
    __syncthreads();   // protect sh[] (WAR vs reads above)
    if ((tid & 31) == 0) { sh[8][wid] = s; sh[9][wid] = ss; }
    __syncthreads();
    s = 0.f; ss = 0.f;
    #pragma unroll
    for (int i = 0; i < 8; i++) { s += sh[8][i]; ss += sh[9][i]; }
    float cmu = s * inv_h;
    float cvar = ss * inv_h - cmu * cmu;
    float crstd = rsqrtf(cvar + 1e-5f);

    float4 cg4 = *(const float4*)(cg + col);
    float4 cb4 = *(const float4*)(cb + col);
    float cgv[4] = {cg4.x, cg4.y, cg4.z, cg4.w};
    float cbv[4] = {cb4.x, cb4.y, cb4.z, cb4.w};

    float oh[4], oc[4];
    #pragma unroll
    for (int j = 0; j < 4; j++) {
        float nc = (cp[j] - cmu) * crstd * cgv[j] + cbv[j];
        oc[j] = nc;
        oh[j] = gate[3][j] * ftanh(nc);
    }
    *(float4*)(outc + (size_t)b * HDIM + col) = make_float4(oc[0], oc[1], oc[2], oc[3]);
    *(float4*)(outh + (size_t)b * HDIM + col) = make_float4(oh[0], oh[1], oh[2], oh[3]);
}

// ---------------- launcher -----------------------------------------------------
extern "C" void kernel_launch(void* const* d_in, const int* in_sizes, int n_in,
                              void* d_out, int out_size) {
    const float* inp = (const float*)d_in[0];
    const float* h   = (const float*)d_in[1];
    const float* c   = (const float*)d_in[2];
    const float* W   = (const float*)d_in[3];
    const float* g4  = (const float*)d_in[4];
    const float* b4  = (const float*)d_in[5];
    const float* cg  = (const float*)d_in[6];
    const float* cb  = (const float*)d_in[7];
    float* out = (float*)d_out;

    cudaFuncSetAttribute(gemm_kernel,
                         cudaFuncAttributeMaxDynamicSharedMemorySize, SMEM_TOTAL);

    conv_a_kernel<<<(int)(((size_t)BDIM * KDIM / 4 + 255) / 256), 256>>>(inp, h);
    conv_w_kernel<<<(int)(((size_t)NDIM * KDIM / 4 + 255) / 256), 256>>>(W);

    dim3 grid(NDIM / TN, BDIM / TM);  // 16 x 64 = 1024 CTAs
    gemm_kernel<<<grid, 256, SMEM_TOTAL>>>();

    ln_kernel<<<BDIM, 256>>>(c, g4, b4, cg, cb,
                             out,                        // new_h
                             out + (size_t)BDIM * HDIM); // new_c
}